// round 12
// baseline (speedup 1.0000x reference)
#include <cuda_runtime.h>
#include <cuda_bf16.h>
#include <cstdint>

// Problem constants (fixed by the dataset)
#define NN 10000      // nodes
#define NE 160000     // directed edges
#define FD 512        // feature dim (IN == H == 512)
#define OUTD 16       // classes
#define BM 144        // GEMM M tile (9 x 16)
#define MTILES 71     // ceil(10000 / 144)
#define M_PAD (BM * MTILES)   // 10224

// ----------------------------------------------------------------------------
// Scratch: __device__ globals (no runtime allocation allowed).
// ----------------------------------------------------------------------------
__device__ int   g_deg[NN];
__device__ int   g_cursor[NN];
__device__ float g_dinv[NN];
__device__ int   g_row_start[NN + 1];
__device__ int   g_csr_src[NE];
__device__ __align__(16) float g_bufA[(size_t)NN * FD];   // GEMM out (fp32)
__device__ __align__(16) __nv_bfloat16 g_Ahi[(size_t)M_PAD * FD];
__device__ __align__(16) __nv_bfloat16 g_Alo[(size_t)M_PAD * FD];
__device__ __align__(16) __nv_bfloat16 g_Whi[2][FD * FD]; // transposed [N][K]
__device__ __align__(16) __nv_bfloat16 g_Wlo[2][FD * FD]; // transposed [N][K]

// SW64 swizzle on byte offsets (64B rows): XOR bits[5:4] with bits[8:7]
#define SWZ64(o) ((o) ^ (((o) >> 3) & 0x30))

__device__ __forceinline__ uint32_t smem_u32(const void* p) {
    uint32_t a;
    asm("{ .reg .u64 t; cvta.to.shared.u64 t, %1; cvt.u32.u64 %0, t; }"
        : "=r"(a) : "l"(p));
    return a;
}
__device__ __forceinline__ void ldmx4(uint32_t addr, uint32_t* r) {
    asm volatile("ldmatrix.sync.aligned.m8n8.x4.shared.b16 {%0,%1,%2,%3}, [%4];"
                 : "=r"(r[0]), "=r"(r[1]), "=r"(r[2]), "=r"(r[3]) : "r"(addr));
}
__device__ __forceinline__ void mma_bf16(float* c, const uint32_t* a,
                                         const uint32_t* b) {
    asm volatile(
        "mma.sync.aligned.m16n8k16.row.col.f32.bf16.bf16.f32 "
        "{%0,%1,%2,%3},{%4,%5,%6,%7},{%8,%9},{%0,%1,%2,%3};"
        : "+f"(c[0]), "+f"(c[1]), "+f"(c[2]), "+f"(c[3])
        : "r"(a[0]), "r"(a[1]), "r"(a[2]), "r"(a[3]), "r"(b[0]), "r"(b[1]));
}
__device__ __forceinline__ void cpasync16(uint32_t s, const void* g) {
    asm volatile("cp.async.cg.shared.global [%0], [%1], 16;" :: "r"(s), "l"(g));
}
#define CP_COMMIT() asm volatile("cp.async.commit_group;")

// Per-block edge_index dtype detection: if buffer is int64, odd words of the
// first 32 elements are high words of values < 2^31 -> all zero.
__device__ __forceinline__ int detect_i64(const int* __restrict__ ei32) {
    int o = 0;
#pragma unroll
    for (int j = 0; j < 32; j++) o |= ei32[2 * j + 1];
    return (o == 0) ? 1 : 0;
}

// ----------------------------------------------------------------------------
// Graph preprocessing
// ----------------------------------------------------------------------------
__global__ void zero_counts_kernel() {
    int i = blockIdx.x * blockDim.x + threadIdx.x;
    if (i < NN) { g_deg[i] = 0; g_cursor[i] = 0; }
}

__global__ void count_kernel(const int* __restrict__ ei32) {
    __shared__ int s_i64;
    if (threadIdx.x == 0) s_i64 = detect_i64(ei32);
    __syncthreads();
    int i = blockIdx.x * blockDim.x + threadIdx.x;
    if (i < NE) {
        int dst = s_i64 ? ei32[2 * (NE + i)] : ei32[NE + i];
        atomicAdd(&g_deg[dst], 1);
    }
}

// Single-block exclusive scan of g_deg -> g_row_start.
__global__ void scan_kernel() {
    __shared__ int sums[1024];
    const int CH = (NN + 1023) / 1024;   // 10
    int t = threadIdx.x;
    int start = t * CH;
    int vals[CH];
    int local = 0;
#pragma unroll
    for (int i = 0; i < CH; i++) {
        int idx = start + i;
        int v = (idx < NN) ? g_deg[idx] : 0;
        vals[i] = v;
        local += v;
    }
    sums[t] = local;
    __syncthreads();
    for (int off = 1; off < 1024; off <<= 1) {
        int v = sums[t];
        int add = (t >= off) ? sums[t - off] : 0;
        __syncthreads();
        sums[t] = v + add;
        __syncthreads();
    }
    int prefix = (t == 0) ? 0 : sums[t - 1];
#pragma unroll
    for (int i = 0; i < CH; i++) {
        int idx = start + i;
        if (idx < NN) { g_row_start[idx] = prefix; prefix += vals[i]; }
    }
    if (t == 1023) g_row_start[NN] = prefix;
}

// CSR fill + grid-wide dinv.
__global__ void fill_kernel(const int* __restrict__ ei32) {
    __shared__ int s_i64;
    if (threadIdx.x == 0) s_i64 = detect_i64(ei32);
    __syncthreads();
    int i = blockIdx.x * blockDim.x + threadIdx.x;
    if (i < NE) {
        int src, dst;
        if (s_i64) { src = ei32[2 * i]; dst = ei32[2 * (NE + i)]; }
        else       { src = ei32[i];     dst = ei32[NE + i]; }
        int pos = atomicAdd(&g_cursor[dst], 1);
        g_csr_src[g_row_start[dst] + pos] = src;
    }
    for (int n = i; n < NN; n += gridDim.x * blockDim.x)
        g_dinv[n] = rsqrtf((float)g_deg[n] + 1.0f);
}

// ----------------------------------------------------------------------------
// fp32 -> bf16 hi/lo split conversions (merged: A split + both W transposes)
// ----------------------------------------------------------------------------
__device__ __forceinline__ uint32_t pk2(__nv_bfloat16 a, __nv_bfloat16 b) {
    __nv_bfloat162 t(a, b);
    return *reinterpret_cast<uint32_t*>(&t);
}
__device__ __forceinline__ void split4(float4 v, uint2& hi, uint2& lo) {
    __nv_bfloat16 h0 = __float2bfloat16(v.x), h1 = __float2bfloat16(v.y);
    __nv_bfloat16 h2 = __float2bfloat16(v.z), h3 = __float2bfloat16(v.w);
    __nv_bfloat16 l0 = __float2bfloat16(v.x - __bfloat162float(h0));
    __nv_bfloat16 l1 = __float2bfloat16(v.y - __bfloat162float(h1));
    __nv_bfloat16 l2 = __float2bfloat16(v.z - __bfloat162float(h2));
    __nv_bfloat16 l3 = __float2bfloat16(v.w - __bfloat162float(h3));
    hi = make_uint2(pk2(h0, h1), pk2(h2, h3));
    lo = make_uint2(pk2(l0, l1), pk2(l2, l3));
}

#define CONVA_ITEMS ((M_PAD * FD) / 4)       // vec4 items for A
#define CONVW_ITEMS (2 * FD * FD)            // scalar items for both W

__global__ __launch_bounds__(256)
void conv_kernel(const float* __restrict__ x, const float* __restrict__ W1,
                 const float* __restrict__ W2) {
    int idx = blockIdx.x * blockDim.x + threadIdx.x;
    if (idx < CONVA_ITEMS) {
        size_t i = (size_t)idx * 4;
        int row = (int)(i >> 9);
        float4 v = make_float4(0.f, 0.f, 0.f, 0.f);
        if (row < NN) v = *(const float4*)(x + i);
        uint2 hi, lo;
        split4(v, hi, lo);
        *(uint2*)(g_Ahi + i) = hi;
        *(uint2*)(g_Alo + i) = lo;
    } else {
        int j = idx - CONVA_ITEMS;
        if (j < CONVW_ITEMS) {
            int layer = j >> 18;                 // / (FD*FD)
            int r = j & (FD * FD - 1);           // output index n*512 + k
            int n = r >> 9, k = r & (FD - 1);
            const float* W = layer ? W2 : W1;
            float v = W[(size_t)k * FD + n];
            __nv_bfloat16 hi = __float2bfloat16(v);
            g_Whi[layer][r] = hi;
            g_Wlo[layer][r] = __float2bfloat16(v - __bfloat162float(hi));
        }
    }
}

// ----------------------------------------------------------------------------
// Split-precision bf16 GEMM via mma.sync, cp.async 3-stage pipeline:
//   g_bufA[M_PAD x 512] = Ahi@Whi^T + Ahi@Wlo^T + Alo@Whi^T   (fp32 accum)
// CTA tile 144x128, grid 4x71 = 284 CTAs = one wave at 2 CTAs/SM.
// 384 threads = 12 warps (3 M x 4 N, warp tile 48x32). BK=32, SW64 64B rows.
// Stage = Ahi 9216 + Alo 9216 + Bhi 8192 + Blo 8192 = 34816 B; 3 stages.
// ----------------------------------------------------------------------------
#define OFF_ALO 9216
#define OFF_BHI 18432
#define OFF_BLO 26624
#define STAGE_BYTES 34816
#define NSTAGE 3
#define GEMM_SMEM   (NSTAGE * STAGE_BYTES)
#define KCHUNKS (FD / 32)                   // 16

template <int LAYER>
__global__ __launch_bounds__(384, 2)
void gemm_mma_kernel() {
    extern __shared__ __align__(1024) char smem[];
    const uint32_t sb = smem_u32(smem);

    const int tid = threadIdx.x;
    const int wid = tid >> 5;
    const int lane = tid & 31;
    const int warp_m = (wid >> 2) * 48;      // 0, 48, 96
    const int warp_n = (wid & 3) * 32;       // 0, 32, 64, 96
    const int blockCol = blockIdx.x * 128;
    const int blockRow = blockIdx.y * BM;

    const __nv_bfloat16* Wh = g_Whi[LAYER];
    const __nv_bfloat16* Wl = g_Wlo[LAYER];

    float acc[3][4][4];
#pragma unroll
    for (int i = 0; i < 3; i++)
#pragma unroll
        for (int j = 0; j < 4; j++)
#pragma unroll
            for (int k = 0; k < 4; k++) acc[i][j][k] = 0.f;

    const int aRowL = (lane & 15);
    const int aKbL  = (lane >> 4) * 16;
    const int bRowL = ((lane >> 4) << 3) + (lane & 7);
    const int bKbL  = ((lane >> 3) & 1) * 16;

    // A: 1152 16B-chunks (Ahi 576 + Alo 576); B: 1024 (Bhi 512 + Blo 512)
#define ISSUE_STAGE(kc, buf) do {                                              \
    uint32_t st = sb + (buf) * STAGE_BYTES;                                    \
    _Pragma("unroll")                                                          \
    for (int t = 0; t < 3; t++) {                                              \
        int idx = tid + t * 384;             /* 0..1151 */                     \
        int mat = (idx >= 576);                                                \
        int r = idx - (mat ? 576 : 0);                                         \
        int row = r >> 2, seg = r & 3;                                         \
        int sw = SWZ64(row * 64 + seg * 16);                                   \
        size_t ga = (size_t)(blockRow + row) * FD + (kc) * 32 + seg * 8;       \
        cpasync16(st + (mat ? OFF_ALO : 0) + sw,                               \
                  (mat ? g_Alo : g_Ahi) + ga);                                 \
    }                                                                          \
    _Pragma("unroll")                                                          \
    for (int t = 0; t < 3; t++) {                                              \
        int idx = tid + t * 384;                                               \
        if (idx < 1024) {                                                      \
            int mat = (idx >= 512);                                            \
            int r = idx - (mat ? 512 : 0);                                     \
            int row = r >> 2, seg = r & 3;                                     \
            int sw = SWZ64(row * 64 + seg * 16);                               \
            size_t gb = (size_t)(blockCol + row) * FD + (kc) * 32 + seg * 8;   \
            cpasync16(st + (mat ? OFF_BLO : OFF_BHI) + sw,                     \
                      (mat ? Wl : Wh) + gb);                                   \
        }                                                                      \
    }                                                                          \
    CP_COMMIT(); } while (0)

    ISSUE_STAGE(0, 0);
    ISSUE_STAGE(1, 1);

    for (int kc = 0; kc < KCHUNKS; kc++) {
        const int buf = kc % NSTAGE;
        if (kc + 2 < KCHUNKS) {
            ISSUE_STAGE(kc + 2, (kc + 2) % NSTAGE);
            asm volatile("cp.async.wait_group 2;");
        } else if (kc + 1 < KCHUNKS) {
            asm volatile("cp.async.wait_group 1;");
        } else {
            asm volatile("cp.async.wait_group 0;");
        }
        __syncthreads();

        const uint32_t st = sb + buf * STAGE_BYTES;
#pragma unroll
        for (int s = 0; s < 2; s++) {
            uint32_t bh[8], bl[8];
#pragma unroll
            for (int p = 0; p < 2; p++) {
                int brow = warp_n + p * 16 + bRowL;
                int boff = SWZ64(brow * 64 + s * 32 + bKbL);
                ldmx4(st + OFF_BHI + boff, &bh[p * 4]);
                ldmx4(st + OFF_BLO + boff, &bl[p * 4]);
            }
#pragma unroll
            for (int mt = 0; mt < 3; mt++) {
                int arow = warp_m + mt * 16 + aRowL;
                int aoff = SWZ64(arow * 64 + s * 32 + aKbL);
                uint32_t ah[4], al[4];
                ldmx4(st + 0 + aoff, ah);
                ldmx4(st + OFF_ALO + aoff, al);
#pragma unroll
                for (int nt = 0; nt < 4; nt++) {
                    mma_bf16(acc[mt][nt], ah, &bh[nt * 2]);
                    mma_bf16(acc[mt][nt], ah, &bl[nt * 2]);
                    mma_bf16(acc[mt][nt], al, &bh[nt * 2]);
                }
            }
        }
        __syncthreads();
    }
#undef ISSUE_STAGE

    const int mBase = blockRow + warp_m + (lane >> 2);
    const int nBase = blockCol + warp_n + (lane & 3) * 2;
#pragma unroll
    for (int mt = 0; mt < 3; mt++) {
        int m0 = mBase + mt * 16;
#pragma unroll
        for (int nt = 0; nt < 4; nt++) {
            int n = nBase + nt * 8;
            if (m0 < NN)
                *(float2*)(g_bufA + (size_t)m0 * FD + n) =
                    make_float2(acc[mt][nt][0], acc[mt][nt][1]);
            if (m0 + 8 < NN)
                *(float2*)(g_bufA + (size_t)(m0 + 8) * FD + n) =
                    make_float2(acc[mt][nt][2], acc[mt][nt][3]);
        }
    }
}

// ----------------------------------------------------------------------------
// Aggregation: acc = sum norm*g_bufA[src] + dinv^2*g_bufA[node] + bias, ReLU.
// HEAD=false: write bf16 hi/lo into g_Ahi/g_Alo (feeds next GEMM).
// HEAD=true:  fuse final linear: out[node] = acc @ Wl + bl (16 classes).
// ----------------------------------------------------------------------------
template <bool HEAD>
__global__ __launch_bounds__(128)
void agg_kernel(const float* __restrict__ bias,
                const float* __restrict__ Wl, const float* __restrict__ bl,
                float* __restrict__ out) {
    const float* h = (const float*)g_bufA;
    int node = blockIdx.x;
    int t = threadIdx.x;
    __shared__ int   s_src[128];
    __shared__ float s_w[128];

    float dd = g_dinv[node];
    float4 acc;
    {
        float4 v = __ldcg((const float4*)(h + (size_t)node * FD) + t);
        float w = dd * dd;
        acc = make_float4(v.x * w, v.y * w, v.z * w, v.w * w);
    }

    int beg = g_row_start[node];
    int end = g_row_start[node + 1];
    for (int c = beg; c < end; c += 128) {
        int n = min(end - c, 128);
        if (t < n) {
            int s = g_csr_src[c + t];
            s_src[t] = s;
            s_w[t] = g_dinv[s] * dd;
        }
        __syncthreads();
        int e = 0;
        for (; e + 3 < n; e += 4) {
            int s0 = s_src[e],     s1 = s_src[e + 1];
            int s2 = s_src[e + 2], s3 = s_src[e + 3];
            float w0 = s_w[e],     w1 = s_w[e + 1];
            float w2 = s_w[e + 2], w3 = s_w[e + 3];
            float4 v0 = __ldcg((const float4*)(h + (size_t)s0 * FD) + t);
            float4 v1 = __ldcg((const float4*)(h + (size_t)s1 * FD) + t);
            float4 v2 = __ldcg((const float4*)(h + (size_t)s2 * FD) + t);
            float4 v3 = __ldcg((const float4*)(h + (size_t)s3 * FD) + t);
            acc.x += w0 * v0.x + w1 * v1.x + w2 * v2.x + w3 * v3.x;
            acc.y += w0 * v0.y + w1 * v1.y + w2 * v2.y + w3 * v3.y;
            acc.z += w0 * v0.z + w1 * v1.z + w2 * v2.z + w3 * v3.z;
            acc.w += w0 * v0.w + w1 * v1.w + w2 * v2.w + w3 * v3.w;
        }
        for (; e < n; e++) {
            int s0 = s_src[e];
            float w0 = s_w[e];
            float4 v0 = __ldcg((const float4*)(h + (size_t)s0 * FD) + t);
            acc.x += w0 * v0.x; acc.y += w0 * v0.y;
            acc.z += w0 * v0.z; acc.w += w0 * v0.w;
        }
        __syncthreads();
    }

    float4 b = *(const float4*)(bias + t * 4);
    acc.x = fmaxf(acc.x + b.x, 0.f);
    acc.y = fmaxf(acc.y + b.y, 0.f);
    acc.z = fmaxf(acc.z + b.z, 0.f);
    acc.w = fmaxf(acc.w + b.w, 0.f);

    if (!HEAD) {
        size_t o = (size_t)node * FD + t * 4;
        uint2 hi, lo;
        split4(acc, hi, lo);
        *(uint2*)(g_Ahi + o) = hi;
        *(uint2*)(g_Alo + o) = lo;
    } else {
        // Fused head: p[c] = sum over this thread's 4 features; Wl is
        // L1-resident (32KB shared by all blocks on the SM).
        float p[OUTD];
        const float4 av = acc;
        const float* wrow = Wl + (size_t)(t * 4) * OUTD;
#pragma unroll
        for (int c = 0; c < OUTD; c++)
            p[c] = av.x * wrow[c] + av.y * wrow[OUTD + c]
                 + av.z * wrow[2 * OUTD + c] + av.w * wrow[3 * OUTD + c];
        // Warp reduction (5 steps), then cross-warp via smem.
#pragma unroll
        for (int off = 16; off > 0; off >>= 1)
#pragma unroll
            for (int c = 0; c < OUTD; c++)
                p[c] += __shfl_down_sync(0xFFFFFFFFu, p[c], off);
        __shared__ float s_part[4][OUTD];
        int wi = t >> 5, ln = t & 31;
        if (ln == 0)
#pragma unroll
            for (int c = 0; c < OUTD; c++) s_part[wi][c] = p[c];
        __syncthreads();
        if (t < OUTD) {
            float r = s_part[0][t] + s_part[1][t] + s_part[2][t] + s_part[3][t];
            out[(size_t)node * OUTD + t] = r + bl[t];
        }
    }
}

// ----------------------------------------------------------------------------
// Side stream + events for fork/join overlap (created once at static init).
// ----------------------------------------------------------------------------
namespace {
struct Aux {
    cudaStream_t s2 = nullptr;
    cudaEvent_t  eFork = nullptr, eJoin = nullptr;
    bool ok = false;
    Aux() {
        if (cudaStreamCreateWithFlags(&s2, cudaStreamNonBlocking) != cudaSuccess)
            return;
        if (cudaEventCreateWithFlags(&eFork, cudaEventDisableTiming) != cudaSuccess)
            return;
        if (cudaEventCreateWithFlags(&eJoin, cudaEventDisableTiming) != cudaSuccess)
            return;
        ok = true;
    }
};
Aux g_aux;
}

// ----------------------------------------------------------------------------
// Launch
// ----------------------------------------------------------------------------
extern "C" void kernel_launch(void* const* d_in, const int* in_sizes, int n_in,
                              void* d_out, int out_size) {
    const float* x  = (const float*)d_in[0];
    const int*   ei = (const int*)d_in[1];
    const float* W1 = (const float*)d_in[2];
    const float* b1 = (const float*)d_in[3];
    const float* W2 = (const float*)d_in[4];
    const float* b2 = (const float*)d_in[5];
    const float* Wl = (const float*)d_in[6];
    const float* bl = (const float*)d_in[7];
    float* out = (float*)d_out;

    cudaFuncSetAttribute(gemm_mma_kernel<0>,
                         cudaFuncAttributeMaxDynamicSharedMemorySize, GEMM_SMEM);
    cudaFuncSetAttribute(gemm_mma_kernel<1>,
                         cudaFuncAttributeMaxDynamicSharedMemorySize, GEMM_SMEM);

    dim3 gemmGrid(FD / 128, MTILES);                      // (4, 71) = 284 CTAs
    int convBlocks = (CONVA_ITEMS + CONVW_ITEMS + 255) / 256;

    if (g_aux.ok) {
        // Fork: CSR preprocessing on side stream, conversions + GEMM-0 on main.
        cudaEventRecord(g_aux.eFork, 0);
        cudaStreamWaitEvent(g_aux.s2, g_aux.eFork, 0);
        zero_counts_kernel<<<(NN + 255) / 256, 256, 0, g_aux.s2>>>();
        count_kernel<<<(NE + 255) / 256, 256, 0, g_aux.s2>>>(ei);
        scan_kernel<<<1, 1024, 0, g_aux.s2>>>();
        fill_kernel<<<(NE + 255) / 256, 256, 0, g_aux.s2>>>(ei);
        cudaEventRecord(g_aux.eJoin, g_aux.s2);

        conv_kernel<<<convBlocks, 256>>>(x, W1, W2);
        gemm_mma_kernel<0><<<gemmGrid, 384, GEMM_SMEM>>>();

        cudaStreamWaitEvent(0, g_aux.eJoin, 0);           // join before agg
    } else {
        // Serial fallback
        zero_counts_kernel<<<(NN + 255) / 256, 256>>>();
        count_kernel<<<(NE + 255) / 256, 256>>>(ei);
        scan_kernel<<<1, 1024>>>();
        fill_kernel<<<(NE + 255) / 256, 256>>>(ei);
        conv_kernel<<<convBlocks, 256>>>(x, W1, W2);
        gemm_mma_kernel<0><<<gemmGrid, 384, GEMM_SMEM>>>();
    }

    // Layer 1 aggregation -> bf16 split input of layer 2
    agg_kernel<false><<<NN, 128>>>(b1, nullptr, nullptr, nullptr);

    // Layer 2 GEMM, then aggregation fused with the linear head
    gemm_mma_kernel<1><<<gemmGrid, 384, GEMM_SMEM>>>();
    agg_kernel<true><<<NN, 128>>>(b2, Wl, bl, out);
}

// round 14
// speedup vs baseline: 2.3482x; 2.3482x over previous
#include <cuda_runtime.h>
#include <cuda_bf16.h>
#include <cstdint>

// Problem constants (fixed by the dataset)
#define NN 10000      // nodes
#define NE 160000     // directed edges
#define FD 512        // feature dim (IN == H == 512)
#define OUTD 16       // classes
#define BM 144        // GEMM M tile (9 x 16)
#define MTILES 71     // ceil(10000 / 144)
#define M_PAD (BM * MTILES)   // 10224

// ----------------------------------------------------------------------------
// Scratch: __device__ globals (no runtime allocation allowed).
// ----------------------------------------------------------------------------
__device__ int   g_deg[NN];
__device__ int   g_cursor[NN];
__device__ float g_dinv[NN];
__device__ int   g_row_start[NN + 1];
__device__ int   g_csr_src[NE];
__device__ __align__(16) float g_bufA[(size_t)NN * FD];   // GEMM out (fp32)
__device__ __align__(16) float g_bufB[(size_t)NN * FD];   // agg2 out (fp32)
__device__ __align__(16) __nv_bfloat16 g_Ahi[(size_t)M_PAD * FD];
__device__ __align__(16) __nv_bfloat16 g_Alo[(size_t)M_PAD * FD];
__device__ __align__(16) __nv_bfloat16 g_Whi[2][FD * FD]; // transposed [N][K]
__device__ __align__(16) __nv_bfloat16 g_Wlo[2][FD * FD]; // transposed [N][K]

// SW64 swizzle on byte offsets (64B rows): XOR bits[5:4] with bits[8:7]
#define SWZ64(o) ((o) ^ (((o) >> 3) & 0x30))

__device__ __forceinline__ uint32_t smem_u32(const void* p) {
    uint32_t a;
    asm("{ .reg .u64 t; cvta.to.shared.u64 t, %1; cvt.u32.u64 %0, t; }"
        : "=r"(a) : "l"(p));
    return a;
}
__device__ __forceinline__ void ldmx4(uint32_t addr, uint32_t* r) {
    asm volatile("ldmatrix.sync.aligned.m8n8.x4.shared.b16 {%0,%1,%2,%3}, [%4];"
                 : "=r"(r[0]), "=r"(r[1]), "=r"(r[2]), "=r"(r[3]) : "r"(addr));
}
__device__ __forceinline__ void mma_bf16(float* c, const uint32_t* a,
                                         const uint32_t* b) {
    asm volatile(
        "mma.sync.aligned.m16n8k16.row.col.f32.bf16.bf16.f32 "
        "{%0,%1,%2,%3},{%4,%5,%6,%7},{%8,%9},{%0,%1,%2,%3};"
        : "+f"(c[0]), "+f"(c[1]), "+f"(c[2]), "+f"(c[3])
        : "r"(a[0]), "r"(a[1]), "r"(a[2]), "r"(a[3]), "r"(b[0]), "r"(b[1]));
}
__device__ __forceinline__ void cpasync16(uint32_t s, const void* g) {
    asm volatile("cp.async.cg.shared.global [%0], [%1], 16;" :: "r"(s), "l"(g));
}
#define CP_COMMIT() asm volatile("cp.async.commit_group;")

// Per-block edge_index dtype detection: if buffer is int64, odd words of the
// first 32 elements are high words of values < 2^31 -> all zero.
__device__ __forceinline__ int detect_i64(const int* __restrict__ ei32) {
    int o = 0;
#pragma unroll
    for (int j = 0; j < 32; j++) o |= ei32[2 * j + 1];
    return (o == 0) ? 1 : 0;
}

// ----------------------------------------------------------------------------
// Graph preprocessing
// ----------------------------------------------------------------------------
__global__ void zero_counts_kernel() {
    int i = blockIdx.x * blockDim.x + threadIdx.x;
    if (i < NN) { g_deg[i] = 0; g_cursor[i] = 0; }
}

__global__ void count_kernel(const int* __restrict__ ei32) {
    __shared__ int s_i64;
    if (threadIdx.x == 0) s_i64 = detect_i64(ei32);
    __syncthreads();
    int i = blockIdx.x * blockDim.x + threadIdx.x;
    if (i < NE) {
        int dst = s_i64 ? ei32[2 * (NE + i)] : ei32[NE + i];
        atomicAdd(&g_deg[dst], 1);
    }
}

// Single-block exclusive scan of g_deg -> g_row_start.
__global__ void scan_kernel() {
    __shared__ int sums[1024];
    const int CH = (NN + 1023) / 1024;   // 10
    int t = threadIdx.x;
    int start = t * CH;
    int vals[CH];
    int local = 0;
#pragma unroll
    for (int i = 0; i < CH; i++) {
        int idx = start + i;
        int v = (idx < NN) ? g_deg[idx] : 0;
        vals[i] = v;
        local += v;
    }
    sums[t] = local;
    __syncthreads();
    for (int off = 1; off < 1024; off <<= 1) {
        int v = sums[t];
        int add = (t >= off) ? sums[t - off] : 0;
        __syncthreads();
        sums[t] = v + add;
        __syncthreads();
    }
    int prefix = (t == 0) ? 0 : sums[t - 1];
#pragma unroll
    for (int i = 0; i < CH; i++) {
        int idx = start + i;
        if (idx < NN) { g_row_start[idx] = prefix; prefix += vals[i]; }
    }
    if (t == 1023) g_row_start[NN] = prefix;
}

// CSR fill + grid-wide dinv.
__global__ void fill_kernel(const int* __restrict__ ei32) {
    __shared__ int s_i64;
    if (threadIdx.x == 0) s_i64 = detect_i64(ei32);
    __syncthreads();
    int i = blockIdx.x * blockDim.x + threadIdx.x;
    if (i < NE) {
        int src, dst;
        if (s_i64) { src = ei32[2 * i]; dst = ei32[2 * (NE + i)]; }
        else       { src = ei32[i];     dst = ei32[NE + i]; }
        int pos = atomicAdd(&g_cursor[dst], 1);
        g_csr_src[g_row_start[dst] + pos] = src;
    }
    for (int n = i; n < NN; n += gridDim.x * blockDim.x)
        g_dinv[n] = rsqrtf((float)g_deg[n] + 1.0f);
}

// ----------------------------------------------------------------------------
// fp32 -> bf16 hi/lo split conversions (merged: A split + both W transposes)
// ----------------------------------------------------------------------------
__device__ __forceinline__ uint32_t pk2(__nv_bfloat16 a, __nv_bfloat16 b) {
    __nv_bfloat162 t(a, b);
    return *reinterpret_cast<uint32_t*>(&t);
}
__device__ __forceinline__ void split4(float4 v, uint2& hi, uint2& lo) {
    __nv_bfloat16 h0 = __float2bfloat16(v.x), h1 = __float2bfloat16(v.y);
    __nv_bfloat16 h2 = __float2bfloat16(v.z), h3 = __float2bfloat16(v.w);
    __nv_bfloat16 l0 = __float2bfloat16(v.x - __bfloat162float(h0));
    __nv_bfloat16 l1 = __float2bfloat16(v.y - __bfloat162float(h1));
    __nv_bfloat16 l2 = __float2bfloat16(v.z - __bfloat162float(h2));
    __nv_bfloat16 l3 = __float2bfloat16(v.w - __bfloat162float(h3));
    hi = make_uint2(pk2(h0, h1), pk2(h2, h3));
    lo = make_uint2(pk2(l0, l1), pk2(l2, l3));
}

#define CONVA_ITEMS ((M_PAD * FD) / 4)       // vec4 items for A
#define CONVW_ITEMS (2 * FD * FD)            // scalar items for both W

__global__ __launch_bounds__(256)
void conv_kernel(const float* __restrict__ x, const float* __restrict__ W1,
                 const float* __restrict__ W2) {
    int idx = blockIdx.x * blockDim.x + threadIdx.x;
    if (idx < CONVA_ITEMS) {
        size_t i = (size_t)idx * 4;
        int row = (int)(i >> 9);
        float4 v = make_float4(0.f, 0.f, 0.f, 0.f);
        if (row < NN) v = *(const float4*)(x + i);
        uint2 hi, lo;
        split4(v, hi, lo);
        *(uint2*)(g_Ahi + i) = hi;
        *(uint2*)(g_Alo + i) = lo;
    } else {
        int j = idx - CONVA_ITEMS;
        if (j < CONVW_ITEMS) {
            int layer = j >> 18;                 // / (FD*FD)
            int r = j & (FD * FD - 1);           // output index n*512 + k
            int n = r >> 9, k = r & (FD - 1);
            const float* W = layer ? W2 : W1;
            float v = W[(size_t)k * FD + n];
            __nv_bfloat16 hi = __float2bfloat16(v);
            g_Whi[layer][r] = hi;
            g_Wlo[layer][r] = __float2bfloat16(v - __bfloat162float(hi));
        }
    }
}

// ----------------------------------------------------------------------------
// Split-precision bf16 GEMM via mma.sync, cp.async 2-stage pipeline (proven R11):
//   g_bufA[M_PAD x 512] = Ahi@Whi^T + Ahi@Wlo^T + Alo@Whi^T   (fp32 accum)
// CTA tile 144x128, grid 4x71 = 284 CTAs = one wave at 2 CTAs/SM.
// 384 threads = 12 warps (3 M x 4 N, warp tile 48x32). BK=32, SW64 64B rows.
// ----------------------------------------------------------------------------
#define OFF_ALO 9216
#define OFF_BHI 18432
#define OFF_BLO 26624
#define STAGE_BYTES 34816
#define GEMM_SMEM   (2 * STAGE_BYTES)

template <int LAYER>
__global__ __launch_bounds__(384, 2)
void gemm_mma_kernel() {
    extern __shared__ __align__(1024) char smem[];
    const uint32_t sb = smem_u32(smem);

    const int tid = threadIdx.x;
    const int wid = tid >> 5;
    const int lane = tid & 31;
    const int warp_m = (wid >> 2) * 48;      // 0, 48, 96
    const int warp_n = (wid & 3) * 32;       // 0, 32, 64, 96
    const int blockCol = blockIdx.x * 128;
    const int blockRow = blockIdx.y * BM;

    const __nv_bfloat16* Wh = g_Whi[LAYER];
    const __nv_bfloat16* Wl = g_Wlo[LAYER];

    float acc[3][4][4];
#pragma unroll
    for (int i = 0; i < 3; i++)
#pragma unroll
        for (int j = 0; j < 4; j++)
#pragma unroll
            for (int k = 0; k < 4; k++) acc[i][j][k] = 0.f;

    const int aRowL = (lane & 15);
    const int aKbL  = (lane >> 4) * 16;
    const int bRowL = ((lane >> 4) << 3) + (lane & 7);
    const int bKbL  = ((lane >> 3) & 1) * 16;

    // A: 1152 16B-chunks (Ahi 576 + Alo 576); B: 1024 (Bhi 512 + Blo 512)
#define ISSUE_STAGE(kc, buf) do {                                              \
    uint32_t st = sb + (buf) * STAGE_BYTES;                                    \
    _Pragma("unroll")                                                          \
    for (int t = 0; t < 3; t++) {                                              \
        int idx = tid + t * 384;             /* 0..1151 */                     \
        int mat = (idx >= 576);                                                \
        int r = idx - (mat ? 576 : 0);                                         \
        int row = r >> 2, seg = r & 3;                                         \
        int sw = SWZ64(row * 64 + seg * 16);                                   \
        size_t ga = (size_t)(blockRow + row) * FD + (kc) * 32 + seg * 8;       \
        cpasync16(st + (mat ? OFF_ALO : 0) + sw,                               \
                  (mat ? g_Alo : g_Ahi) + ga);                                 \
    }                                                                          \
    _Pragma("unroll")                                                          \
    for (int t = 0; t < 3; t++) {                                              \
        int idx = tid + t * 384;                                               \
        if (idx < 1024) {                                                      \
            int mat = (idx >= 512);                                            \
            int r = idx - (mat ? 512 : 0);                                     \
            int row = r >> 2, seg = r & 3;                                     \
            int sw = SWZ64(row * 64 + seg * 16);                               \
            size_t gb = (size_t)(blockCol + row) * FD + (kc) * 32 + seg * 8;   \
            cpasync16(st + (mat ? OFF_BLO : OFF_BHI) + sw,                     \
                      (mat ? Wl : Wh) + gb);                                   \
        }                                                                      \
    }                                                                          \
    CP_COMMIT(); } while (0)

    ISSUE_STAGE(0, 0);

    for (int kc = 0; kc < FD / 32; kc++) {
        const int buf = kc & 1;
        if (kc < FD / 32 - 1) {
            ISSUE_STAGE(kc + 1, buf ^ 1);
            asm volatile("cp.async.wait_group 1;");
        } else {
            asm volatile("cp.async.wait_group 0;");
        }
        __syncthreads();

        const uint32_t st = sb + buf * STAGE_BYTES;
#pragma unroll
        for (int s = 0; s < 2; s++) {
            uint32_t bh[8], bl[8];
#pragma unroll
            for (int p = 0; p < 2; p++) {
                int brow = warp_n + p * 16 + bRowL;
                int boff = SWZ64(brow * 64 + s * 32 + bKbL);
                ldmx4(st + OFF_BHI + boff, &bh[p * 4]);
                ldmx4(st + OFF_BLO + boff, &bl[p * 4]);
            }
#pragma unroll
            for (int mt = 0; mt < 3; mt++) {
                int arow = warp_m + mt * 16 + aRowL;
                int aoff = SWZ64(arow * 64 + s * 32 + aKbL);
                uint32_t ah[4], al[4];
                ldmx4(st + 0 + aoff, ah);
                ldmx4(st + OFF_ALO + aoff, al);
#pragma unroll
                for (int nt = 0; nt < 4; nt++) {
                    mma_bf16(acc[mt][nt], ah, &bh[nt * 2]);
                    mma_bf16(acc[mt][nt], ah, &bl[nt * 2]);
                    mma_bf16(acc[mt][nt], al, &bh[nt * 2]);
                }
            }
        }
        __syncthreads();
    }
#undef ISSUE_STAGE

    const int mBase = blockRow + warp_m + (lane >> 2);
    const int nBase = blockCol + warp_n + (lane & 3) * 2;
#pragma unroll
    for (int mt = 0; mt < 3; mt++) {
        int m0 = mBase + mt * 16;
#pragma unroll
        for (int nt = 0; nt < 4; nt++) {
            int n = nBase + nt * 8;
            if (m0 < NN)
                *(float2*)(g_bufA + (size_t)m0 * FD + n) =
                    make_float2(acc[mt][nt][0], acc[mt][nt][1]);
            if (m0 + 8 < NN)
                *(float2*)(g_bufA + (size_t)(m0 + 8) * FD + n) =
                    make_float2(acc[mt][nt][2], acc[mt][nt][3]);
        }
    }
}

// ----------------------------------------------------------------------------
// Aggregation: acc = sum norm*g_bufA[src] + dinv^2*g_bufA[node] + bias, ReLU.
// Unroll x8 for MLP (avg degree ~16 -> 2 latency waves instead of 4).
// SPLIT=true: write bf16 hi/lo into g_Ahi/g_Alo. SPLIT=false: fp32 g_bufB.
// ----------------------------------------------------------------------------
template <bool SPLIT>
__global__ __launch_bounds__(128)
void agg_kernel(const float* __restrict__ bias) {
    const float* h = (const float*)g_bufA;
    int node = blockIdx.x;
    int t = threadIdx.x;
    __shared__ int   s_src[128];
    __shared__ float s_w[128];

    float dd = g_dinv[node];
    float4 acc;
    {
        float4 v = __ldcg((const float4*)(h + (size_t)node * FD) + t);
        float w = dd * dd;
        acc = make_float4(v.x * w, v.y * w, v.z * w, v.w * w);
    }

    int beg = g_row_start[node];
    int end = g_row_start[node + 1];
    for (int c = beg; c < end; c += 128) {
        int n = min(end - c, 128);
        if (t < n) {
            int s = g_csr_src[c + t];
            s_src[t] = s;
            s_w[t] = g_dinv[s] * dd;
        }
        __syncthreads();
        int e = 0;
        for (; e + 7 < n; e += 8) {
            float4 v[8];
            float  w[8];
#pragma unroll
            for (int u = 0; u < 8; u++) {
                int s0 = s_src[e + u];
                w[u] = s_w[e + u];
                v[u] = __ldcg((const float4*)(h + (size_t)s0 * FD) + t);
            }
#pragma unroll
            for (int u = 0; u < 8; u++) {
                acc.x += w[u] * v[u].x;
                acc.y += w[u] * v[u].y;
                acc.z += w[u] * v[u].z;
                acc.w += w[u] * v[u].w;
            }
        }
        for (; e + 3 < n; e += 4) {
            float4 v[4];
            float  w[4];
#pragma unroll
            for (int u = 0; u < 4; u++) {
                int s0 = s_src[e + u];
                w[u] = s_w[e + u];
                v[u] = __ldcg((const float4*)(h + (size_t)s0 * FD) + t);
            }
#pragma unroll
            for (int u = 0; u < 4; u++) {
                acc.x += w[u] * v[u].x;
                acc.y += w[u] * v[u].y;
                acc.z += w[u] * v[u].z;
                acc.w += w[u] * v[u].w;
            }
        }
        for (; e < n; e++) {
            int s0 = s_src[e];
            float w0 = s_w[e];
            float4 v0 = __ldcg((const float4*)(h + (size_t)s0 * FD) + t);
            acc.x += w0 * v0.x; acc.y += w0 * v0.y;
            acc.z += w0 * v0.z; acc.w += w0 * v0.w;
        }
        __syncthreads();
    }

    float4 b = *(const float4*)(bias + t * 4);
    acc.x = fmaxf(acc.x + b.x, 0.f);
    acc.y = fmaxf(acc.y + b.y, 0.f);
    acc.z = fmaxf(acc.z + b.z, 0.f);
    acc.w = fmaxf(acc.w + b.w, 0.f);

    size_t o = (size_t)node * FD + t * 4;
    if (SPLIT) {
        uint2 hi, lo;
        split4(acc, hi, lo);
        *(uint2*)(g_Ahi + o) = hi;
        *(uint2*)(g_Alo + o) = lo;
    } else {
        *(float4*)(g_bufB + o) = acc;
    }
}

// ----------------------------------------------------------------------------
// Final linear: out[N x 16] = g_bufB @ Wl + bl
// ----------------------------------------------------------------------------
__global__ __launch_bounds__(256)
void linear16_kernel(const float* __restrict__ W, const float* __restrict__ b,
                     float* __restrict__ out) {
    const float* h = (const float*)g_bufB;
    __shared__ float sW[FD * OUTD];
    int t = threadIdx.x;
    for (int i = t; i < FD * OUTD; i += 256) sW[i] = W[i];
    __syncthreads();

    int r = t >> 4;
    int c = t & 15;
    int row = blockIdx.x * 16 + r;
    if (row >= NN) return;

    const float4* hp = (const float4*)(h + (size_t)row * FD);
    float acc = 0.f;
#pragma unroll 4
    for (int k = 0; k < FD / 4; k++) {
        float4 v = hp[k];
        acc += v.x * sW[(4 * k + 0) * OUTD + c];
        acc += v.y * sW[(4 * k + 1) * OUTD + c];
        acc += v.z * sW[(4 * k + 2) * OUTD + c];
        acc += v.w * sW[(4 * k + 3) * OUTD + c];
    }
    out[(size_t)row * OUTD + c] = acc + b[c];
}

// ----------------------------------------------------------------------------
// Side stream + events for fork/join overlap (created once at static init).
// ----------------------------------------------------------------------------
namespace {
struct Aux {
    cudaStream_t s2 = nullptr;
    cudaEvent_t  eFork = nullptr, eJoin = nullptr;
    bool ok = false;
    Aux() {
        if (cudaStreamCreateWithFlags(&s2, cudaStreamNonBlocking) != cudaSuccess)
            return;
        if (cudaEventCreateWithFlags(&eFork, cudaEventDisableTiming) != cudaSuccess)
            return;
        if (cudaEventCreateWithFlags(&eJoin, cudaEventDisableTiming) != cudaSuccess)
            return;
        ok = true;
    }
};
Aux g_aux;
}

// ----------------------------------------------------------------------------
// Launch
// ----------------------------------------------------------------------------
extern "C" void kernel_launch(void* const* d_in, const int* in_sizes, int n_in,
                              void* d_out, int out_size) {
    const float* x  = (const float*)d_in[0];
    const int*   ei = (const int*)d_in[1];
    const float* W1 = (const float*)d_in[2];
    const float* b1 = (const float*)d_in[3];
    const float* W2 = (const float*)d_in[4];
    const float* b2 = (const float*)d_in[5];
    const float* Wl = (const float*)d_in[6];
    const float* bl = (const float*)d_in[7];
    float* out = (float*)d_out;

    cudaFuncSetAttribute(gemm_mma_kernel<0>,
                         cudaFuncAttributeMaxDynamicSharedMemorySize, GEMM_SMEM);
    cudaFuncSetAttribute(gemm_mma_kernel<1>,
                         cudaFuncAttributeMaxDynamicSharedMemorySize, GEMM_SMEM);

    dim3 gemmGrid(FD / 128, MTILES);                      // (4, 71) = 284 CTAs
    int convBlocks = (CONVA_ITEMS + CONVW_ITEMS + 255) / 256;

    if (g_aux.ok) {
        // Fork: CSR preprocessing on side stream, conversions + GEMM-0 on main.
        cudaEventRecord(g_aux.eFork, 0);
        cudaStreamWaitEvent(g_aux.s2, g_aux.eFork, 0);
        zero_counts_kernel<<<(NN + 255) / 256, 256, 0, g_aux.s2>>>();
        count_kernel<<<(NE + 255) / 256, 256, 0, g_aux.s2>>>(ei);
        scan_kernel<<<1, 1024, 0, g_aux.s2>>>();
        fill_kernel<<<(NE + 255) / 256, 256, 0, g_aux.s2>>>(ei);
        cudaEventRecord(g_aux.eJoin, g_aux.s2);

        conv_kernel<<<convBlocks, 256>>>(x, W1, W2);
        gemm_mma_kernel<0><<<gemmGrid, 384, GEMM_SMEM>>>();

        cudaStreamWaitEvent(0, g_aux.eJoin, 0);           // join before agg
    } else {
        // Serial fallback
        zero_counts_kernel<<<(NN + 255) / 256, 256>>>();
        count_kernel<<<(NE + 255) / 256, 256>>>(ei);
        scan_kernel<<<1, 1024>>>();
        fill_kernel<<<(NE + 255) / 256, 256>>>(ei);
        conv_kernel<<<convBlocks, 256>>>(x, W1, W2);
        gemm_mma_kernel<0><<<gemmGrid, 384, GEMM_SMEM>>>();
    }

    // Layer 1 aggregation -> bf16 split input of layer 2
    agg_kernel<true><<<NN, 128>>>(b1);

    // Layer 2
    gemm_mma_kernel<1><<<gemmGrid, 384, GEMM_SMEM>>>();
    agg_kernel<false><<<NN, 128>>>(b2);

    // Head
    linear16_kernel<<<(NN + 15) / 16, 256>>>(Wl, bl, out);
}

// round 16
// speedup vs baseline: 2.6251x; 1.1179x over previous
#include <cuda_runtime.h>
#include <cuda_bf16.h>
#include <cstdint>

// Problem constants (fixed by the dataset)
#define NN 10000      // nodes
#define NE 160000     // directed edges
#define FD 512        // feature dim (IN == H == 512)
#define OUTD 16       // classes
#define BM 144        // GEMM M tile (9 x 16)
#define MTILES 71     // ceil(10000 / 144)
#define M_PAD (BM * MTILES)   // 10224

// ----------------------------------------------------------------------------
// Scratch: __device__ globals (no runtime allocation allowed).
// ----------------------------------------------------------------------------
__device__ int   g_deg[NN];
__device__ int   g_cursor[NN];
__device__ float g_dinv[NN];
__device__ int   g_row_start[NN + 1];
__device__ int   g_csr_src[NE];
__device__ __align__(16) float g_bufA[(size_t)NN * FD];   // GEMM out (fp32)
__device__ __align__(16) float g_WlT[OUTD * FD];          // head W transposed
__device__ __align__(16) __nv_bfloat16 g_Ahi[(size_t)M_PAD * FD];
__device__ __align__(16) __nv_bfloat16 g_Alo[(size_t)M_PAD * FD];
__device__ __align__(16) __nv_bfloat16 g_Whi[2][FD * FD]; // transposed [N][K]
__device__ __align__(16) __nv_bfloat16 g_Wlo[2][FD * FD]; // transposed [N][K]

// SW64 swizzle on byte offsets (64B rows): XOR bits[5:4] with bits[8:7]
#define SWZ64(o) ((o) ^ (((o) >> 3) & 0x30))

__device__ __forceinline__ uint32_t smem_u32(const void* p) {
    uint32_t a;
    asm("{ .reg .u64 t; cvta.to.shared.u64 t, %1; cvt.u32.u64 %0, t; }"
        : "=r"(a) : "l"(p));
    return a;
}
__device__ __forceinline__ void ldmx4(uint32_t addr, uint32_t* r) {
    asm volatile("ldmatrix.sync.aligned.m8n8.x4.shared.b16 {%0,%1,%2,%3}, [%4];"
                 : "=r"(r[0]), "=r"(r[1]), "=r"(r[2]), "=r"(r[3]) : "r"(addr));
}
__device__ __forceinline__ void mma_bf16(float* c, const uint32_t* a,
                                         const uint32_t* b) {
    asm volatile(
        "mma.sync.aligned.m16n8k16.row.col.f32.bf16.bf16.f32 "
        "{%0,%1,%2,%3},{%4,%5,%6,%7},{%8,%9},{%0,%1,%2,%3};"
        : "+f"(c[0]), "+f"(c[1]), "+f"(c[2]), "+f"(c[3])
        : "r"(a[0]), "r"(a[1]), "r"(a[2]), "r"(a[3]), "r"(b[0]), "r"(b[1]));
}
__device__ __forceinline__ void cpasync16(uint32_t s, const void* g) {
    asm volatile("cp.async.cg.shared.global [%0], [%1], 16;" :: "r"(s), "l"(g));
}
#define CP_COMMIT() asm volatile("cp.async.commit_group;")

// Per-block edge_index dtype detection: if buffer is int64, odd words of the
// first 32 elements are high words of values < 2^31 -> all zero.
__device__ __forceinline__ int detect_i64(const int* __restrict__ ei32) {
    int o = 0;
#pragma unroll
    for (int j = 0; j < 32; j++) o |= ei32[2 * j + 1];
    return (o == 0) ? 1 : 0;
}

// ----------------------------------------------------------------------------
// Graph preprocessing
// ----------------------------------------------------------------------------
__global__ void zero_counts_kernel() {
    int i = blockIdx.x * blockDim.x + threadIdx.x;
    if (i < NN) { g_deg[i] = 0; g_cursor[i] = 0; }
}

__global__ void count_kernel(const int* __restrict__ ei32) {
    __shared__ int s_i64;
    if (threadIdx.x == 0) s_i64 = detect_i64(ei32);
    __syncthreads();
    int i = blockIdx.x * blockDim.x + threadIdx.x;
    if (i < NE) {
        int dst = s_i64 ? ei32[2 * (NE + i)] : ei32[NE + i];
        atomicAdd(&g_deg[dst], 1);
    }
}

// Single-block exclusive scan of g_deg -> g_row_start.
__global__ void scan_kernel() {
    __shared__ int sums[1024];
    const int CH = (NN + 1023) / 1024;   // 10
    int t = threadIdx.x;
    int start = t * CH;
    int vals[CH];
    int local = 0;
#pragma unroll
    for (int i = 0; i < CH; i++) {
        int idx = start + i;
        int v = (idx < NN) ? g_deg[idx] : 0;
        vals[i] = v;
        local += v;
    }
    sums[t] = local;
    __syncthreads();
    for (int off = 1; off < 1024; off <<= 1) {
        int v = sums[t];
        int add = (t >= off) ? sums[t - off] : 0;
        __syncthreads();
        sums[t] = v + add;
        __syncthreads();
    }
    int prefix = (t == 0) ? 0 : sums[t - 1];
#pragma unroll
    for (int i = 0; i < CH; i++) {
        int idx = start + i;
        if (idx < NN) { g_row_start[idx] = prefix; prefix += vals[i]; }
    }
    if (t == 1023) g_row_start[NN] = prefix;
}

// CSR fill + grid-wide dinv.
__global__ void fill_kernel(const int* __restrict__ ei32) {
    __shared__ int s_i64;
    if (threadIdx.x == 0) s_i64 = detect_i64(ei32);
    __syncthreads();
    int i = blockIdx.x * blockDim.x + threadIdx.x;
    if (i < NE) {
        int src, dst;
        if (s_i64) { src = ei32[2 * i]; dst = ei32[2 * (NE + i)]; }
        else       { src = ei32[i];     dst = ei32[NE + i]; }
        int pos = atomicAdd(&g_cursor[dst], 1);
        g_csr_src[g_row_start[dst] + pos] = src;
    }
    for (int n = i; n < NN; n += gridDim.x * blockDim.x)
        g_dinv[n] = rsqrtf((float)g_deg[n] + 1.0f);
}

// ----------------------------------------------------------------------------
// fp32 -> bf16 hi/lo split conversions (merged: A split + both W transposes
// + head-weight transpose WlT[c][f] = Wl[f][c])
// ----------------------------------------------------------------------------
__device__ __forceinline__ uint32_t pk2(__nv_bfloat16 a, __nv_bfloat16 b) {
    __nv_bfloat162 t(a, b);
    return *reinterpret_cast<uint32_t*>(&t);
}
__device__ __forceinline__ void split4(float4 v, uint2& hi, uint2& lo) {
    __nv_bfloat16 h0 = __float2bfloat16(v.x), h1 = __float2bfloat16(v.y);
    __nv_bfloat16 h2 = __float2bfloat16(v.z), h3 = __float2bfloat16(v.w);
    __nv_bfloat16 l0 = __float2bfloat16(v.x - __bfloat162float(h0));
    __nv_bfloat16 l1 = __float2bfloat16(v.y - __bfloat162float(h1));
    __nv_bfloat16 l2 = __float2bfloat16(v.z - __bfloat162float(h2));
    __nv_bfloat16 l3 = __float2bfloat16(v.w - __bfloat162float(h3));
    hi = make_uint2(pk2(h0, h1), pk2(h2, h3));
    lo = make_uint2(pk2(l0, l1), pk2(l2, l3));
}

#define CONVA_ITEMS ((M_PAD * FD) / 4)       // vec4 items for A
#define CONVW_ITEMS (2 * FD * FD)            // scalar items for both W
#define CONVH_ITEMS (OUTD * FD)              // scalar items for WlT

__global__ __launch_bounds__(256)
void conv_kernel(const float* __restrict__ x, const float* __restrict__ W1,
                 const float* __restrict__ W2, const float* __restrict__ Wl) {
    int idx = blockIdx.x * blockDim.x + threadIdx.x;
    if (idx < CONVA_ITEMS) {
        size_t i = (size_t)idx * 4;
        int row = (int)(i >> 9);
        float4 v = make_float4(0.f, 0.f, 0.f, 0.f);
        if (row < NN) v = *(const float4*)(x + i);
        uint2 hi, lo;
        split4(v, hi, lo);
        *(uint2*)(g_Ahi + i) = hi;
        *(uint2*)(g_Alo + i) = lo;
    } else {
        int j = idx - CONVA_ITEMS;
        if (j < CONVW_ITEMS) {
            int layer = j >> 18;                 // / (FD*FD)
            int r = j & (FD * FD - 1);           // output index n*512 + k
            int n = r >> 9, k = r & (FD - 1);
            const float* W = layer ? W2 : W1;
            float v = W[(size_t)k * FD + n];
            __nv_bfloat16 hi = __float2bfloat16(v);
            g_Whi[layer][r] = hi;
            g_Wlo[layer][r] = __float2bfloat16(v - __bfloat162float(hi));
        } else {
            int j2 = j - CONVW_ITEMS;            // WlT: c*512 + f
            if (j2 < CONVH_ITEMS) {
                int c = j2 >> 9, f = j2 & (FD - 1);
                g_WlT[j2] = Wl[(size_t)f * OUTD + c];
            }
        }
    }
}

// ----------------------------------------------------------------------------
// Split-precision bf16 GEMM via mma.sync, cp.async 2-stage pipeline (proven R11):
//   g_bufA[M_PAD x 512] = Ahi@Whi^T + Ahi@Wlo^T + Alo@Whi^T   (fp32 accum)
// CTA tile 144x128, grid 4x71 = 284 CTAs = one wave at 2 CTAs/SM.
// 384 threads = 12 warps (3 M x 4 N, warp tile 48x32). BK=32, SW64 64B rows.
// ----------------------------------------------------------------------------
#define OFF_ALO 9216
#define OFF_BHI 18432
#define OFF_BLO 26624
#define STAGE_BYTES 34816
#define GEMM_SMEM   (2 * STAGE_BYTES)

template <int LAYER>
__global__ __launch_bounds__(384, 2)
void gemm_mma_kernel() {
    extern __shared__ __align__(1024) char smem[];
    const uint32_t sb = smem_u32(smem);

    const int tid = threadIdx.x;
    const int wid = tid >> 5;
    const int lane = tid & 31;
    const int warp_m = (wid >> 2) * 48;      // 0, 48, 96
    const int warp_n = (wid & 3) * 32;       // 0, 32, 64, 96
    const int blockCol = blockIdx.x * 128;
    const int blockRow = blockIdx.y * BM;

    const __nv_bfloat16* Wh = g_Whi[LAYER];
    const __nv_bfloat16* Wl = g_Wlo[LAYER];

    float acc[3][4][4];
#pragma unroll
    for (int i = 0; i < 3; i++)
#pragma unroll
        for (int j = 0; j < 4; j++)
#pragma unroll
            for (int k = 0; k < 4; k++) acc[i][j][k] = 0.f;

    const int aRowL = (lane & 15);
    const int aKbL  = (lane >> 4) * 16;
    const int bRowL = ((lane >> 4) << 3) + (lane & 7);
    const int bKbL  = ((lane >> 3) & 1) * 16;

    // A: 1152 16B-chunks (Ahi 576 + Alo 576); B: 1024 (Bhi 512 + Blo 512)
#define ISSUE_STAGE(kc, buf) do {                                              \
    uint32_t st = sb + (buf) * STAGE_BYTES;                                    \
    _Pragma("unroll")                                                          \
    for (int t = 0; t < 3; t++) {                                              \
        int idx = tid + t * 384;             /* 0..1151 */                     \
        int mat = (idx >= 576);                                                \
        int r = idx - (mat ? 576 : 0);                                         \
        int row = r >> 2, seg = r & 3;                                         \
        int sw = SWZ64(row * 64 + seg * 16);                                   \
        size_t ga = (size_t)(blockRow + row) * FD + (kc) * 32 + seg * 8;       \
        cpasync16(st + (mat ? OFF_ALO : 0) + sw,                               \
                  (mat ? g_Alo : g_Ahi) + ga);                                 \
    }                                                                          \
    _Pragma("unroll")                                                          \
    for (int t = 0; t < 3; t++) {                                              \
        int idx = tid + t * 384;                                               \
        if (idx < 1024) {                                                      \
            int mat = (idx >= 512);                                            \
            int r = idx - (mat ? 512 : 0);                                     \
            int row = r >> 2, seg = r & 3;                                     \
            int sw = SWZ64(row * 64 + seg * 16);                               \
            size_t gb = (size_t)(blockCol + row) * FD + (kc) * 32 + seg * 8;   \
            cpasync16(st + (mat ? OFF_BLO : OFF_BHI) + sw,                     \
                      (mat ? Wl : Wh) + gb);                                   \
        }                                                                      \
    }                                                                          \
    CP_COMMIT(); } while (0)

    ISSUE_STAGE(0, 0);

    for (int kc = 0; kc < FD / 32; kc++) {
        const int buf = kc & 1;
        if (kc < FD / 32 - 1) {
            ISSUE_STAGE(kc + 1, buf ^ 1);
            asm volatile("cp.async.wait_group 1;");
        } else {
            asm volatile("cp.async.wait_group 0;");
        }
        __syncthreads();

        const uint32_t st = sb + buf * STAGE_BYTES;
#pragma unroll
        for (int s = 0; s < 2; s++) {
            uint32_t bh[8], bl[8];
#pragma unroll
            for (int p = 0; p < 2; p++) {
                int brow = warp_n + p * 16 + bRowL;
                int boff = SWZ64(brow * 64 + s * 32 + bKbL);
                ldmx4(st + OFF_BHI + boff, &bh[p * 4]);
                ldmx4(st + OFF_BLO + boff, &bl[p * 4]);
            }
#pragma unroll
            for (int mt = 0; mt < 3; mt++) {
                int arow = warp_m + mt * 16 + aRowL;
                int aoff = SWZ64(arow * 64 + s * 32 + aKbL);
                uint32_t ah[4], al[4];
                ldmx4(st + 0 + aoff, ah);
                ldmx4(st + OFF_ALO + aoff, al);
#pragma unroll
                for (int nt = 0; nt < 4; nt++) {
                    mma_bf16(acc[mt][nt], ah, &bh[nt * 2]);
                    mma_bf16(acc[mt][nt], ah, &bl[nt * 2]);
                    mma_bf16(acc[mt][nt], al, &bh[nt * 2]);
                }
            }
        }
        __syncthreads();
    }
#undef ISSUE_STAGE

    const int mBase = blockRow + warp_m + (lane >> 2);
    const int nBase = blockCol + warp_n + (lane & 3) * 2;
#pragma unroll
    for (int mt = 0; mt < 3; mt++) {
        int m0 = mBase + mt * 16;
#pragma unroll
        for (int nt = 0; nt < 4; nt++) {
            int n = nBase + nt * 8;
            if (m0 < NN)
                *(float2*)(g_bufA + (size_t)m0 * FD + n) =
                    make_float2(acc[mt][nt][0], acc[mt][nt][1]);
            if (m0 + 8 < NN)
                *(float2*)(g_bufA + (size_t)(m0 + 8) * FD + n) =
                    make_float2(acc[mt][nt][2], acc[mt][nt][3]);
        }
    }
}

// ----------------------------------------------------------------------------
// Aggregation: acc = sum norm*g_bufA[src] + dinv^2*g_bufA[node] + bias, ReLU.
// HEAD=false: write bf16 hi/lo into g_Ahi/g_Alo (feeds next GEMM).
// HEAD=true:  fused head with COALESCED WlT access: stage acc row in smem,
//             each warp computes 4 classes (lane-contiguous float4 reads of
//             WlT, L1-resident across blocks), shuffle-reduce, lane0 writes.
// ----------------------------------------------------------------------------
template <bool HEAD>
__global__ __launch_bounds__(128)
void agg_kernel(const float* __restrict__ bias,
                const float* __restrict__ bl, float* __restrict__ out) {
    const float* h = (const float*)g_bufA;
    int node = blockIdx.x;
    int t = threadIdx.x;
    __shared__ int   s_src[128];
    __shared__ float s_w[128];

    float dd = g_dinv[node];
    float4 acc;
    {
        float4 v = __ldcg((const float4*)(h + (size_t)node * FD) + t);
        float w = dd * dd;
        acc = make_float4(v.x * w, v.y * w, v.z * w, v.w * w);
    }

    int beg = g_row_start[node];
    int end = g_row_start[node + 1];
    for (int c = beg; c < end; c += 128) {
        int n = min(end - c, 128);
        if (t < n) {
            int s = g_csr_src[c + t];
            s_src[t] = s;
            s_w[t] = g_dinv[s] * dd;
        }
        __syncthreads();
        int e = 0;
        for (; e + 7 < n; e += 8) {
            float4 v[8];
            float  w[8];
#pragma unroll
            for (int u = 0; u < 8; u++) {
                int s0 = s_src[e + u];
                w[u] = s_w[e + u];
                v[u] = __ldcg((const float4*)(h + (size_t)s0 * FD) + t);
            }
#pragma unroll
            for (int u = 0; u < 8; u++) {
                acc.x += w[u] * v[u].x;
                acc.y += w[u] * v[u].y;
                acc.z += w[u] * v[u].z;
                acc.w += w[u] * v[u].w;
            }
        }
        for (; e + 3 < n; e += 4) {
            float4 v[4];
            float  w[4];
#pragma unroll
            for (int u = 0; u < 4; u++) {
                int s0 = s_src[e + u];
                w[u] = s_w[e + u];
                v[u] = __ldcg((const float4*)(h + (size_t)s0 * FD) + t);
            }
#pragma unroll
            for (int u = 0; u < 4; u++) {
                acc.x += w[u] * v[u].x;
                acc.y += w[u] * v[u].y;
                acc.z += w[u] * v[u].z;
                acc.w += w[u] * v[u].w;
            }
        }
        for (; e < n; e++) {
            int s0 = s_src[e];
            float w0 = s_w[e];
            float4 v0 = __ldcg((const float4*)(h + (size_t)s0 * FD) + t);
            acc.x += w0 * v0.x; acc.y += w0 * v0.y;
            acc.z += w0 * v0.z; acc.w += w0 * v0.w;
        }
        __syncthreads();
    }

    float4 b = *(const float4*)(bias + t * 4);
    acc.x = fmaxf(acc.x + b.x, 0.f);
    acc.y = fmaxf(acc.y + b.y, 0.f);
    acc.z = fmaxf(acc.z + b.z, 0.f);
    acc.w = fmaxf(acc.w + b.w, 0.f);

    if (!HEAD) {
        size_t o = (size_t)node * FD + t * 4;
        uint2 hi, lo;
        split4(acc, hi, lo);
        *(uint2*)(g_Ahi + o) = hi;
        *(uint2*)(g_Alo + o) = lo;
    } else {
        // Fused head. s_h[f] = activation row; warp w -> classes 4w..4w+3.
        __shared__ __align__(16) float s_h[FD];
        *(float4*)(s_h + t * 4) = acc;
        __syncthreads();
        int w = t >> 5, l = t & 31;
        float p0 = 0.f, p1 = 0.f, p2 = 0.f, p3 = 0.f;
#pragma unroll
        for (int i = 0; i < 4; i++) {
            int f = l * 4 + i * 128;
            float4 hv = *(const float4*)(s_h + f);
            float4 w0 = *(const float4*)(g_WlT + (4 * w + 0) * FD + f);
            float4 w1 = *(const float4*)(g_WlT + (4 * w + 1) * FD + f);
            float4 w2 = *(const float4*)(g_WlT + (4 * w + 2) * FD + f);
            float4 w3 = *(const float4*)(g_WlT + (4 * w + 3) * FD + f);
            p0 += hv.x * w0.x + hv.y * w0.y + hv.z * w0.z + hv.w * w0.w;
            p1 += hv.x * w1.x + hv.y * w1.y + hv.z * w1.z + hv.w * w1.w;
            p2 += hv.x * w2.x + hv.y * w2.y + hv.z * w2.z + hv.w * w2.w;
            p3 += hv.x * w3.x + hv.y * w3.y + hv.z * w3.z + hv.w * w3.w;
        }
#pragma unroll
        for (int off = 16; off > 0; off >>= 1) {
            p0 += __shfl_down_sync(0xFFFFFFFFu, p0, off);
            p1 += __shfl_down_sync(0xFFFFFFFFu, p1, off);
            p2 += __shfl_down_sync(0xFFFFFFFFu, p2, off);
            p3 += __shfl_down_sync(0xFFFFFFFFu, p3, off);
        }
        if (l == 0) {
            float* op = out + (size_t)node * OUTD + 4 * w;
            op[0] = p0 + bl[4 * w + 0];
            op[1] = p1 + bl[4 * w + 1];
            op[2] = p2 + bl[4 * w + 2];
            op[3] = p3 + bl[4 * w + 3];
        }
    }
}

// ----------------------------------------------------------------------------
// Side stream + events for fork/join overlap (created once at static init).
// ----------------------------------------------------------------------------
namespace {
struct Aux {
    cudaStream_t s2 = nullptr;
    cudaEvent_t  eFork = nullptr, eJoin = nullptr;
    bool ok = false;
    Aux() {
        if (cudaStreamCreateWithFlags(&s2, cudaStreamNonBlocking) != cudaSuccess)
            return;
        if (cudaEventCreateWithFlags(&eFork, cudaEventDisableTiming) != cudaSuccess)
            return;
        if (cudaEventCreateWithFlags(&eJoin, cudaEventDisableTiming) != cudaSuccess)
            return;
        ok = true;
    }
};
Aux g_aux;
}

// ----------------------------------------------------------------------------
// Launch
// ----------------------------------------------------------------------------
extern "C" void kernel_launch(void* const* d_in, const int* in_sizes, int n_in,
                              void* d_out, int out_size) {
    const float* x  = (const float*)d_in[0];
    const int*   ei = (const int*)d_in[1];
    const float* W1 = (const float*)d_in[2];
    const float* b1 = (const float*)d_in[3];
    const float* W2 = (const float*)d_in[4];
    const float* b2 = (const float*)d_in[5];
    const float* Wl = (const float*)d_in[6];
    const float* bl = (const float*)d_in[7];
    float* out = (float*)d_out;

    cudaFuncSetAttribute(gemm_mma_kernel<0>,
                         cudaFuncAttributeMaxDynamicSharedMemorySize, GEMM_SMEM);
    cudaFuncSetAttribute(gemm_mma_kernel<1>,
                         cudaFuncAttributeMaxDynamicSharedMemorySize, GEMM_SMEM);

    dim3 gemmGrid(FD / 128, MTILES);                      // (4, 71) = 284 CTAs
    int convBlocks = (CONVA_ITEMS + CONVW_ITEMS + CONVH_ITEMS + 255) / 256;

    if (g_aux.ok) {
        // Fork: CSR preprocessing on side stream, conversions + GEMM-0 on main.
        cudaEventRecord(g_aux.eFork, 0);
        cudaStreamWaitEvent(g_aux.s2, g_aux.eFork, 0);
        zero_counts_kernel<<<(NN + 255) / 256, 256, 0, g_aux.s2>>>();
        count_kernel<<<(NE + 255) / 256, 256, 0, g_aux.s2>>>(ei);
        scan_kernel<<<1, 1024, 0, g_aux.s2>>>();
        fill_kernel<<<(NE + 255) / 256, 256, 0, g_aux.s2>>>(ei);
        cudaEventRecord(g_aux.eJoin, g_aux.s2);

        conv_kernel<<<convBlocks, 256>>>(x, W1, W2, Wl);
        gemm_mma_kernel<0><<<gemmGrid, 384, GEMM_SMEM>>>();

        cudaStreamWaitEvent(0, g_aux.eJoin, 0);           // join before agg
    } else {
        // Serial fallback
        zero_counts_kernel<<<(NN + 255) / 256, 256>>>();
        count_kernel<<<(NE + 255) / 256, 256>>>(ei);
        scan_kernel<<<1, 1024>>>();
        fill_kernel<<<(NE + 255) / 256, 256>>>(ei);
        conv_kernel<<<convBlocks, 256>>>(x, W1, W2, Wl);
        gemm_mma_kernel<0><<<gemmGrid, 384, GEMM_SMEM>>>();
    }

    // Layer 1 aggregation -> bf16 split input of layer 2
    agg_kernel<false><<<NN, 128>>>(b1, nullptr, nullptr);

    // Layer 2 GEMM, then aggregation with fused (coalesced) head
    gemm_mma_kernel<1><<<gemmGrid, 384, GEMM_SMEM>>>();
    agg_kernel<true><<<NN, 128>>>(b2, bl, out);
}